// round 2
// baseline (speedup 1.0000x reference)
#include <cuda_runtime.h>
#include <math.h>

// Problem constants (B=128, T=512, X=64, H=256)
#define B_     128
#define T_     512
#define X_     64
#define H_     256
#define KK     320            // H + X combined contraction
#define NGATE  128            // 16 b-groups x 8 k-groups
#define NOUT   16             // 16 b-groups
#define GRID_  (NGATE + NOUT) // 144 CTAs, <= 148 SMs -> co-resident
#define NTHR   320            // 10 warps

// -------- gate-CTA smem layout (floats) --------
// Wq   : float4[KK][32]          40960 floats (163840 B)  offset 0
// hid  : float [8][KK]            2560 floats             offset 40960
// red  : float [10][8][32][3]     7680 floats             offset 43520
// total 51200 floats = 204800 B
// -------- out-CTA smem layout (floats) --------
// Ws2  : float2[H][32]           16384 floats  offset 0
// s    : float [8][H]             2048 floats  offset 16384
// red2 : float2[8][8][32]         4096 floats  offset 18432
#define SMEM_BYTES 204800

// GRU hidden history buf[t][b][k] (write-once per slot per launch)
__device__ float    g_buf[(size_t)T_ * B_ * H_];
__device__ unsigned g_bar;

__global__ void init_kernel() { g_bar = 0u; }

// Grid-wide barrier: release fence + atomic arrive, thread0 polls, acquire fence.
__device__ __forceinline__ void gbar(unsigned target) {
    __syncthreads();
    if (threadIdx.x == 0) {
        __threadfence();                 // release: prior .cg stores visible at L2
        atomicAdd(&g_bar, 1u);
        while (*(volatile unsigned*)&g_bar < target) { }
        __threadfence();                 // acquire
    }
    __syncthreads();
}

extern __shared__ float smem[];

__global__ void __launch_bounds__(NTHR, 1) decoder_kernel(
    const float* __restrict__ h_enc,
    const float* __restrict__ W_ih,
    const float* __restrict__ W_hh,
    const float* __restrict__ b_ih,
    const float* __restrict__ b_hh,
    const float* __restrict__ W_out,
    const float* __restrict__ b_out,
    const int*   __restrict__ mask0,
    const int*   __restrict__ mask1,
    const int*   __restrict__ skipp,
    float*       __restrict__ out)
{
    const int tid  = threadIdx.x;
    const int cta  = blockIdx.x;
    const int skip = skipp ? skipp[0] : 4;
    unsigned barno = 0;

    if (cta < NGATE) {
        // ================= GATE CTA: 8 batch rows x 32 hidden cols =================
        const int b0 = (cta >> 3) * 8;
        const int k0 = (cta & 7) * 32;

        float4* Wq  = (float4*)smem;        // [KK][32] of (w_r, w_z, w_n, 0)
        float*  hid = smem + 40960;         // [8][KK]
        float*  red = smem + 43520;         // [10][8][32][3]

        // ---- stage weights once: row k of each gate, contraction-major ----
        for (int i = tid; i < KK * 32; i += NTHR) {
            int kk = i >> 5, kl = i & 31;
            int k  = k0 + kl;
            float r, z, n;
            if (kk < H_) {
                r = W_hh[(size_t)k * H_ + kk];
                z = W_hh[(size_t)(k + H_) * H_ + kk];
                n = W_hh[(size_t)(k + 2 * H_) * H_ + kk];
            } else {
                int xx = kk - H_;
                r = W_ih[k * X_ + xx];
                z = W_ih[(k + H_) * X_ + xx];
                n = W_ih[(k + 2 * H_) * X_ + xx];
            }
            Wq[i] = make_float4(r, z, n, 0.0f);
        }

        // finalize-thread biases (tid < 256 covers the 8x32 output slice)
        float br = 0.f, bz = 0.f, bnh = 0.f, bni = 0.f;
        if (tid < 256) {
            int k = k0 + (tid & 31);
            br  = b_ih[k] + b_hh[k];
            bz  = b_ih[k + H_] + b_hh[k + H_];
            bnh = b_hh[k + 2 * H_];
            bni = b_ih[k + 2 * H_];
        }
        const int kl = tid & 31;
        const int q  = tid >> 5;           // 0..9 contraction segment (32 wide)
        __syncthreads();

        for (int t = 0; t < T_; ++t) {
            // ---- skip tables (generic in skip; matches reference) ----
            int  pg   = (t < skip) ? 2 * t : (t - skip);
            bool gz   = pg < skip;
            int  gidx = pg - skip; if (gidx < 0) gidx = 0;
            int  pp   = (t < skip) ? 2 * t + 1 : (t - skip);
            bool pz   = pp < skip;
            int  pidx = pp - skip; if (pidx < 0) pidx = 0;
            bool late = (!pz) && (pidx >= t);    // projection needs same-step h

            float m0 = (float)__ldg(mask0 + t);
            float m1 = (float)__ldg(mask1 + t);

            // ---- stage combined input vector hid[bl][kk] ----
            // kk < 256: gated hidden = h(t-1)*m0 + buf[gidx]*m1 ; kk >= 256: x = out(t-1)
            const float* hprev = (t == 0) ? h_enc : (g_buf + (size_t)(t - 1) * B_ * H_);
            const float* gsrc  = g_buf + (size_t)gidx * B_ * H_;
            {
                int kk = tid;  // 0..319
                if (kk < H_) {
                    #pragma unroll
                    for (int j = 0; j < 8; ++j) {
                        int b = b0 + j;
                        float hp = (t == 0) ? __ldg(hprev + (size_t)b * H_ + kk)
                                            : __ldcg(hprev + (size_t)b * H_ + kk);
                        float sg = gz ? 0.0f : __ldcg(gsrc + (size_t)b * H_ + kk);
                        hid[j * KK + kk] = hp * m0 + sg * m1;
                    }
                } else {
                    int xx = kk - H_;
                    #pragma unroll
                    for (int j = 0; j < 8; ++j) {
                        int b = b0 + j;
                        float v = (t == 0) ? 0.0f
                                 : __ldcg(out + ((size_t)b * T_ + (t - 1)) * X_ + xx);
                        hid[j * KK + kk] = v;
                    }
                }
            }
            __syncthreads();

            // ---- GEMM partials: this thread: k-col kl, contraction kk in [q*32, q*32+32) ----
            float ar[8], az[8], an[8];
            #pragma unroll
            for (int bl = 0; bl < 8; ++bl) { ar[bl] = 0.f; az[bl] = 0.f; an[bl] = 0.f; }
            const float4* wp = Wq + q * 32 * 32 + kl;
            const float*  hp = hid + q * 32;
            #pragma unroll 8
            for (int i = 0; i < 32; ++i) {
                float4 w = wp[i * 32];
                float hv[8];
                #pragma unroll
                for (int bl = 0; bl < 8; ++bl) hv[bl] = hp[bl * KK + i];
                #pragma unroll
                for (int bl = 0; bl < 8; ++bl) {
                    ar[bl] = fmaf(w.x, hv[bl], ar[bl]);
                    az[bl] = fmaf(w.y, hv[bl], az[bl]);
                    an[bl] = fmaf(w.z, hv[bl], an[bl]);
                }
            }
            #pragma unroll
            for (int bl = 0; bl < 8; ++bl) {
                float* p = red + (((q * 8 + bl) * 32) + kl) * 3;
                p[0] = ar[bl]; p[1] = az[bl]; p[2] = an[bl];
            }
            __syncthreads();

            // ---- finalize: GRU nonlinearity, write h(t) ----
            if (tid < 256) {
                int bl = tid >> 5, klf = tid & 31;
                float sr = 0.f, sz = 0.f, snh = 0.f, sni = 0.f;
                #pragma unroll
                for (int qq = 0; qq < 10; ++qq) {
                    const float* p = red + (((qq * 8 + bl) * 32) + klf) * 3;
                    sr += p[0]; sz += p[1];
                    if (qq < 8) snh += p[2]; else sni += p[2];
                }
                float r  = 1.0f / (1.0f + expf(-(sr + br)));
                float z  = 1.0f / (1.0f + expf(-(sz + bz)));
                float n  = tanhf(sni + bni + r * (snh + bnh));
                float hv = hid[bl * KK + (k0 + klf)];       // gated hidden at feature k
                float hn = (1.0f - z) * n + z * hv;
                __stcg(g_buf + ((size_t)t * B_ + (b0 + bl)) * H_ + (k0 + klf), hn);
            }

            ++barno; gbar(barno * GRID_);
            if (late) { ++barno; gbar(barno * GRID_); }   // idle sub-phase (out CTAs work)
        }
    } else {
        // ================= OUT CTA: projection for 8 batch rows =================
        const int oc = cta - NGATE;
        const int b0 = oc * 8;
        float2* Ws2  = (float2*)smem;          // [H][32] pairs: (W_out[2xh][kk], W_out[2xh+1][kk])
        float*  s    = smem + 16384;           // [8][H]
        float2* red2 = (float2*)(smem + 18432);// [8 q][8 bl][32 xh]

        for (int i = tid; i < H_ * 32; i += NTHR) {
            int kk = i >> 5, xh = i & 31;
            Ws2[i] = make_float2(W_out[(size_t)(2 * xh) * H_ + kk],
                                 W_out[(size_t)(2 * xh + 1) * H_ + kk]);
        }
        float bo0 = 0.f, bo1 = 0.f;
        if (tid < 256) {
            int xh = tid & 31;
            bo0 = b_out[2 * xh];
            bo1 = b_out[2 * xh + 1];
        }
        __syncthreads();

        for (int t = 0; t < T_; ++t) {
            int  pp   = (t < skip) ? 2 * t + 1 : (t - skip);
            bool pz   = pp < skip;
            int  pidx = pp - skip; if (pidx < 0) pidx = 0;
            bool late = (!pz) && (pidx >= t);
            int  npass = late ? 2 : 1;

            for (int pass = 0; pass < npass; ++pass) {
                bool doit = late ? (pass == 1) : (pass == 0);
                if (doit) {
                    // stage s[bl][kk] = h(t-1) + skip_p
                    const float* hprev = (t == 0) ? h_enc : (g_buf + (size_t)(t - 1) * B_ * H_);
                    const float* psrc  = g_buf + (size_t)pidx * B_ * H_;
                    for (int e = tid; e < 8 * H_; e += NTHR) {
                        int bl = e >> 8, kk = e & 255;
                        int b = b0 + bl;
                        float v = (t == 0) ? __ldg(hprev + (size_t)b * H_ + kk)
                                           : __ldcg(hprev + (size_t)b * H_ + kk);
                        if (!pz) v += __ldcg(psrc + (size_t)b * H_ + kk);
                        s[e] = v;
                    }
                    __syncthreads();

                    if (tid < 256) {
                        int xh = tid & 31, qq = tid >> 5;   // 2 x-cols, 32-wide contraction seg
                        float c0[8], c1[8];
                        #pragma unroll
                        for (int bl = 0; bl < 8; ++bl) { c0[bl] = 0.f; c1[bl] = 0.f; }
                        #pragma unroll 8
                        for (int i = 0; i < 32; ++i) {
                            int kk = qq * 32 + i;
                            float2 w = Ws2[kk * 32 + xh];
                            #pragma unroll
                            for (int bl = 0; bl < 8; ++bl) {
                                float sv = s[bl * H_ + kk];
                                c0[bl] = fmaf(w.x, sv, c0[bl]);
                                c1[bl] = fmaf(w.y, sv, c1[bl]);
                            }
                        }
                        #pragma unroll
                        for (int bl = 0; bl < 8; ++bl)
                            red2[(qq * 8 + bl) * 32 + xh] = make_float2(c0[bl], c1[bl]);
                    }
                    __syncthreads();

                    if (tid < 256) {
                        int bl = tid >> 5, xh = tid & 31;
                        float a0 = bo0, a1 = bo1;
                        #pragma unroll
                        for (int qq = 0; qq < 8; ++qq) {
                            float2 v = red2[(qq * 8 + bl) * 32 + xh];
                            a0 += v.x; a1 += v.y;
                        }
                        size_t o = ((size_t)(b0 + bl) * T_ + t) * X_ + 2 * xh;
                        __stcg((float2*)(out + o), make_float2(a0, a1));
                    }
                    __syncthreads();  // protect s/red2 reuse before next phase's barrier
                }
                ++barno; gbar(barno * GRID_);
            }
        }
    }
}

extern "C" void kernel_launch(void* const* d_in, const int* in_sizes, int n_in,
                              void* d_out, int out_size) {
    // metadata order: input, h_enc, W_ih, W_hh, b_ih, b_hh, W_out, b_out, mask0, mask1, skip_size
    const float* h_enc = (const float*)d_in[1];
    const float* W_ih  = (const float*)d_in[2];
    const float* W_hh  = (const float*)d_in[3];
    const float* b_ih  = (const float*)d_in[4];
    const float* b_hh  = (const float*)d_in[5];
    const float* W_out = (const float*)d_in[6];
    const float* b_out = (const float*)d_in[7];
    const int*   mask0 = (const int*)d_in[8];
    const int*   mask1 = (const int*)d_in[9];
    const int*   skipp = (n_in > 10) ? (const int*)d_in[10] : (const int*)0;

    cudaFuncSetAttribute(decoder_kernel,
                         cudaFuncAttributeMaxDynamicSharedMemorySize, SMEM_BYTES);
    init_kernel<<<1, 1>>>();
    decoder_kernel<<<GRID_, NTHR, SMEM_BYTES>>>(
        h_enc, W_ih, W_hh, b_ih, b_hh, W_out, b_out, mask0, mask1, skipp,
        (float*)d_out);
}

// round 3
// speedup vs baseline: 1.0498x; 1.0498x over previous
#include <cuda_runtime.h>
#include <math.h>

// Problem constants (B=128, T=512, X=64, H=256)
#define B_     128
#define T_     512
#define X_     64
#define H_     256
#define KK     320            // H + X combined contraction
#define NGATE  128            // 16 b-groups x 8 k-groups
#define NOUT   16             // 16 b-groups
#define GRID_  (NGATE + NOUT) // 144 CTAs <= 148 SMs -> co-resident
#define NTHR   320            // 10 warps
#define NGROUP 16
#define GSIZE  9              // CTAs per group (8 gate + 1 out)

// -------- gate-CTA smem layout (floats) --------
// Wrz : float2[KK][32]   20480 floats   offset 0
// Wn  : float [KK][32]   10240 floats   offset 20480
// hid : float [KK][8]     2560 floats   offset 30720   (kk-major, batch contiguous)
// red : float [10][8][32][3] 7680 floats offset 33280
// total 40960 floats = 163840 B
// -------- out-CTA smem layout (floats) --------
// Ws2 : float2[H][32]    16384 floats   offset 0
// s   : float [8][H]      2048 floats   offset 16384
// red2: float2[8][8][32]  4096 floats   offset 18432
#define SMEM_BYTES 163840

// GRU hidden history buf[t][b][k] (write-once per slot per launch)
__device__ float    g_buf[(size_t)T_ * B_ * H_];
__device__ unsigned g_bars[NGROUP * 32];   // one counter per 128B line

__global__ void init_kernel() {
    int i = threadIdx.x;
    if (i < NGROUP * 32) g_bars[i] = 0u;
}

// ---- packed f32x2 helpers (Blackwell FFMA2) ----
__device__ __forceinline__ unsigned long long pk2(float a, float b) {
    unsigned long long r;
    asm("mov.b64 %0, {%1, %2};" : "=l"(r) : "f"(a), "f"(b));
    return r;
}
__device__ __forceinline__ void fma2(unsigned long long& d,
                                     unsigned long long a, unsigned long long b) {
    asm("fma.rn.f32x2 %0, %1, %2, %0;" : "+l"(d) : "l"(a), "l"(b));
}
__device__ __forceinline__ float2 up2(unsigned long long v) {
    float2 r;
    asm("mov.b64 {%0, %1}, %2;" : "=f"(r.x), "=f"(r.y) : "l"(v));
    return r;
}

// Per-group barrier: release fence + atomic arrive, thread0 polls, acquire fence.
__device__ __forceinline__ void gbar(int g, unsigned target) {
    __syncthreads();
    if (threadIdx.x == 0) {
        __threadfence();
        atomicAdd(&g_bars[g * 32], 1u);
        while (*(volatile unsigned*)&g_bars[g * 32] < target) { }
        __threadfence();
    }
    __syncthreads();
}

__device__ __forceinline__ float sig_fast(float x) {
    return 1.0f / (1.0f + __expf(-x));
}
__device__ __forceinline__ float tanh_fast(float x) {
    x = fminf(15.0f, fmaxf(-15.0f, x));
    float e = __expf(-2.0f * x);
    return (1.0f - e) / (1.0f + e);
}

extern __shared__ float smem[];

__global__ void __launch_bounds__(NTHR, 1) decoder_kernel(
    const float* __restrict__ h_enc,
    const float* __restrict__ W_ih,
    const float* __restrict__ W_hh,
    const float* __restrict__ b_ih,
    const float* __restrict__ b_hh,
    const float* __restrict__ W_out,
    const float* __restrict__ b_out,
    const int*   __restrict__ mask0,
    const int*   __restrict__ mask1,
    const int*   __restrict__ skipp,
    float*       __restrict__ out)
{
    const int tid  = threadIdx.x;
    const int cta  = blockIdx.x;
    const int skip = skipp ? skipp[0] : 4;
    unsigned barno = 0;

    if (cta < NGATE) {
        // ================= GATE CTA: 8 batch rows x 32 hidden cols =================
        const int grp = cta >> 3;
        const int b0  = grp * 8;
        const int k0  = (cta & 7) * 32;

        float2* Wrz = (float2*)smem;        // [KK][32] of (w_r, w_z)
        float*  Wn  = smem + 20480;         // [KK][32]
        float*  hid = smem + 30720;         // [kk][8]  batch-contiguous
        float*  red = smem + 33280;         // [10][8][32][3]

        // ---- stage weights once ----
        for (int i = tid; i < KK * 32; i += NTHR) {
            int kk = i >> 5, kl = i & 31;
            int k  = k0 + kl;
            float r, z, n;
            if (kk < H_) {
                r = W_hh[(size_t)k * H_ + kk];
                z = W_hh[(size_t)(k + H_) * H_ + kk];
                n = W_hh[(size_t)(k + 2 * H_) * H_ + kk];
            } else {
                int xx = kk - H_;
                r = W_ih[k * X_ + xx];
                z = W_ih[(k + H_) * X_ + xx];
                n = W_ih[(k + 2 * H_) * X_ + xx];
            }
            Wrz[i] = make_float2(r, z);
            Wn[i]  = n;
        }

        // finalize-thread biases (tid < 256 covers the 8x32 output slice)
        float br = 0.f, bz = 0.f, bnh = 0.f, bni = 0.f;
        if (tid < 256) {
            int k = k0 + (tid & 31);
            br  = b_ih[k] + b_hh[k];
            bz  = b_ih[k + H_] + b_hh[k + H_];
            bnh = b_hh[k + 2 * H_];
            bni = b_ih[k + 2 * H_];
        }
        const int kl = tid & 31;
        const int q  = tid >> 5;           // 0..9 contraction segment (32 wide)

        const float2* wrzp = Wrz + q * 32 * 32 + kl;
        const float*  wnp  = Wn  + q * 32 * 32 + kl;
        const unsigned hb  = (unsigned)__cvta_generic_to_shared(hid) + q * 32 * 32; // bytes
        __syncthreads();

        for (int t = 0; t < T_; ++t) {
            // ---- skip tables (generic in skip; matches reference) ----
            int  pg   = (t < skip) ? 2 * t : (t - skip);
            bool gz   = pg < skip;
            int  gidx = pg - skip; if (gidx < 0) gidx = 0;
            int  pp   = (t < skip) ? 2 * t + 1 : (t - skip);
            bool pz   = pp < skip;
            int  pidx = pp - skip; if (pidx < 0) pidx = 0;
            bool late = (!pz) && (pidx >= t);    // projection needs same-step h

            float m0 = (float)__ldg(mask0 + t);
            float m1 = (float)__ldg(mask1 + t);

            // ---- stage combined input vector hid[kk][bl] ----
            const float* hprev = (t == 0) ? h_enc : (g_buf + (size_t)(t - 1) * B_ * H_);
            const float* gsrc  = g_buf + (size_t)gidx * B_ * H_;
            {
                int kk = tid;  // 0..319
                float v[8];
                if (kk < H_) {
                    #pragma unroll
                    for (int j = 0; j < 8; ++j) {
                        int b = b0 + j;
                        float hp = __ldcg(hprev + (size_t)b * H_ + kk);
                        float sg = gz ? 0.0f : __ldcg(gsrc + (size_t)b * H_ + kk);
                        v[j] = hp * m0 + sg * m1;
                    }
                } else {
                    int xx = kk - H_;
                    #pragma unroll
                    for (int j = 0; j < 8; ++j) {
                        int b = b0 + j;
                        v[j] = (t == 0) ? 0.0f
                               : __ldcg(out + ((size_t)b * T_ + (t - 1)) * X_ + xx);
                    }
                }
                float4* hw = (float4*)(hid + kk * 8);
                hw[0] = make_float4(v[0], v[1], v[2], v[3]);
                hw[1] = make_float4(v[4], v[5], v[6], v[7]);
            }
            __syncthreads();

            // ---- packed GEMM partials: k-col kl, contraction seg q ----
            unsigned long long ar[4], az[4], an[4];
            #pragma unroll
            for (int p = 0; p < 4; ++p) { ar[p] = 0ull; az[p] = 0ull; an[p] = 0ull; }
            #pragma unroll
            for (int i = 0; i < 32; ++i) {
                float2 wrzv = wrzp[i * 32];
                float  wnv  = wnp[i * 32];
                unsigned long long wr2 = pk2(wrzv.x, wrzv.x);
                unsigned long long wz2 = pk2(wrzv.y, wrzv.y);
                unsigned long long wn2 = pk2(wnv, wnv);
                unsigned long long h01, h23, h45, h67;
                asm("ld.shared.v2.u64 {%0, %1}, [%2];"
                    : "=l"(h01), "=l"(h23) : "r"(hb + i * 32));
                asm("ld.shared.v2.u64 {%0, %1}, [%2];"
                    : "=l"(h45), "=l"(h67) : "r"(hb + i * 32 + 16));
                fma2(ar[0], wr2, h01); fma2(ar[1], wr2, h23);
                fma2(ar[2], wr2, h45); fma2(ar[3], wr2, h67);
                fma2(az[0], wz2, h01); fma2(az[1], wz2, h23);
                fma2(az[2], wz2, h45); fma2(az[3], wz2, h67);
                fma2(an[0], wn2, h01); fma2(an[1], wn2, h23);
                fma2(an[2], wn2, h45); fma2(an[3], wn2, h67);
            }
            #pragma unroll
            for (int p = 0; p < 4; ++p) {
                float2 r2 = up2(ar[p]), z2 = up2(az[p]), n2 = up2(an[p]);
                float* pa = red + (((q * 8 + 2 * p) * 32) + kl) * 3;
                float* pb = red + (((q * 8 + 2 * p + 1) * 32) + kl) * 3;
                pa[0] = r2.x; pa[1] = z2.x; pa[2] = n2.x;
                pb[0] = r2.y; pb[1] = z2.y; pb[2] = n2.y;
            }
            __syncthreads();

            // ---- finalize: GRU nonlinearity, write h(t) ----
            if (tid < 256) {
                int bl = tid >> 5, klf = tid & 31;
                float sr = 0.f, sz = 0.f, snh = 0.f, sni = 0.f;
                #pragma unroll
                for (int qq = 0; qq < 10; ++qq) {
                    const float* p = red + (((qq * 8 + bl) * 32) + klf) * 3;
                    sr += p[0]; sz += p[1];
                    if (qq < 8) snh += p[2]; else sni += p[2];
                }
                float r  = sig_fast(sr + br);
                float z  = sig_fast(sz + bz);
                float n  = tanh_fast(sni + bni + r * (snh + bnh));
                float hv = hid[(k0 + klf) * 8 + bl];       // gated hidden at feature k
                float hn = (1.0f - z) * n + z * hv;
                __stcg(g_buf + ((size_t)t * B_ + (b0 + bl)) * H_ + (k0 + klf), hn);
            }

            ++barno; gbar(grp, barno * GSIZE);
            if (late) { ++barno; gbar(grp, barno * GSIZE); }   // idle sub-phase
        }
    } else {
        // ================= OUT CTA: projection for 8 batch rows =================
        const int grp = cta - NGATE;
        const int b0  = grp * 8;
        float2* Ws2  = (float2*)smem;          // [H][32]: (W_out[2xh][kk], W_out[2xh+1][kk])
        float*  s    = smem + 16384;           // [8][H]
        float2* red2 = (float2*)(smem + 18432);// [8 q][8 bl][32 xh]

        for (int i = tid; i < H_ * 32; i += NTHR) {
            int kk = i >> 5, xh = i & 31;
            Ws2[i] = make_float2(W_out[(size_t)(2 * xh) * H_ + kk],
                                 W_out[(size_t)(2 * xh + 1) * H_ + kk]);
        }
        float bo0 = 0.f, bo1 = 0.f;
        if (tid < 256) {
            int xh = tid & 31;
            bo0 = b_out[2 * xh];
            bo1 = b_out[2 * xh + 1];
        }
        __syncthreads();

        for (int t = 0; t < T_; ++t) {
            int  pp   = (t < skip) ? 2 * t + 1 : (t - skip);
            bool pz   = pp < skip;
            int  pidx = pp - skip; if (pidx < 0) pidx = 0;
            bool late = (!pz) && (pidx >= t);
            int  npass = late ? 2 : 1;

            for (int pass = 0; pass < npass; ++pass) {
                bool doit = late ? (pass == 1) : (pass == 0);
                if (doit) {
                    // stage s[bl][kk] = h(t-1) + skip_p
                    const float* hprev = (t == 0) ? h_enc : (g_buf + (size_t)(t - 1) * B_ * H_);
                    const float* psrc  = g_buf + (size_t)pidx * B_ * H_;
                    for (int e = tid; e < 8 * H_; e += NTHR) {
                        int bl = e >> 8, kk = e & 255;
                        int b = b0 + bl;
                        float v = __ldcg(hprev + (size_t)b * H_ + kk);
                        if (!pz) v += __ldcg(psrc + (size_t)b * H_ + kk);
                        s[e] = v;
                    }
                    __syncthreads();

                    if (tid < 256) {
                        int xh = tid & 31, qq = tid >> 5;   // 2 x-cols, 32-wide seg
                        float c0[8], c1[8];
                        #pragma unroll
                        for (int bl = 0; bl < 8; ++bl) { c0[bl] = 0.f; c1[bl] = 0.f; }
                        #pragma unroll 8
                        for (int i = 0; i < 32; ++i) {
                            int kk = qq * 32 + i;
                            float2 w = Ws2[kk * 32 + xh];
                            #pragma unroll
                            for (int bl = 0; bl < 8; ++bl) {
                                float sv = s[bl * H_ + kk];
                                c0[bl] = fmaf(w.x, sv, c0[bl]);
                                c1[bl] = fmaf(w.y, sv, c1[bl]);
                            }
                        }
                        #pragma unroll
                        for (int bl = 0; bl < 8; ++bl)
                            red2[(qq * 8 + bl) * 32 + xh] = make_float2(c0[bl], c1[bl]);
                    }
                    __syncthreads();

                    if (tid < 256) {
                        int bl = tid >> 5, xh = tid & 31;
                        float a0 = bo0, a1 = bo1;
                        #pragma unroll
                        for (int qq = 0; qq < 8; ++qq) {
                            float2 v = red2[(qq * 8 + bl) * 32 + xh];
                            a0 += v.x; a1 += v.y;
                        }
                        size_t o = ((size_t)(b0 + bl) * T_ + t) * X_ + 2 * xh;
                        __stcg((float2*)(out + o), make_float2(a0, a1));
                    }
                    __syncthreads();
                }
                ++barno; gbar(grp, barno * GSIZE);
            }
        }
    }
}

extern "C" void kernel_launch(void* const* d_in, const int* in_sizes, int n_in,
                              void* d_out, int out_size) {
    // metadata order: input, h_enc, W_ih, W_hh, b_ih, b_hh, W_out, b_out, mask0, mask1, skip_size
    const float* h_enc = (const float*)d_in[1];
    const float* W_ih  = (const float*)d_in[2];
    const float* W_hh  = (const float*)d_in[3];
    const float* b_ih  = (const float*)d_in[4];
    const float* b_hh  = (const float*)d_in[5];
    const float* W_out = (const float*)d_in[6];
    const float* b_out = (const float*)d_in[7];
    const int*   mask0 = (const int*)d_in[8];
    const int*   mask1 = (const int*)d_in[9];
    const int*   skipp = (n_in > 10) ? (const int*)d_in[10] : (const int*)0;

    cudaFuncSetAttribute(decoder_kernel,
                         cudaFuncAttributeMaxDynamicSharedMemorySize, SMEM_BYTES);
    init_kernel<<<1, NGROUP * 32>>>();
    decoder_kernel<<<GRID_, NTHR, SMEM_BYTES>>>(
        h_enc, W_ih, W_hh, b_ih, b_hh, W_out, b_out, mask0, mask1, skipp,
        (float*)d_out);
}